// round 8
// baseline (speedup 1.0000x reference)
#include <cuda_runtime.h>
#include <math.h>

// SimDiff with shared-target chains + rolling target buffer (low-reg).
//   right[f,i] = cos(x[f,i], x[f+1,i+1]),  valid i <= 550
//   down [f,i] = cos(x[f,i], x[f+1,i+24]), valid i <= 527
// down(f,i) and right(f,i+23) share target row x[f+1,i+24]: a warp walks
// i, i+23, ..., carrying ONE target row that is replaced chunk-by-chunk
// (t_cur[k] consumed for 'right' just before t_next[k] overwrites it).
// 2k+1 row loads per 2k outputs (ratio 2.125 at k=8). Frame 63 = -1 fill.

#define FRAMES 64
#define WIDTH  24
#define TPF    552
#define HID    1152
#define TOTAL  (FRAMES * TPF)     // 35328
#define EPS    1e-8f

#define SEG    8                  // positions per warp segment
#define CHPF   23                 // chains per frame
#define SPC    3                  // segments per chain
#define WPF    (CHPF * SPC)       // 69 warps per frame
#define NWARPS ((FRAMES - 1) * WPF)  // 4347 compute warps
#define ROWQ   (HID / 4)          // 288 float4 per row

__global__ void __launch_bounds__(128, 6)
chain_kernel(const float* __restrict__ x, float* __restrict__ out) {
    const int w    = (blockIdx.x * blockDim.x + threadIdx.x) >> 5;
    const int lane = threadIdx.x & 31;
    if (w >= NWARPS) return;

    const int f  = w / WPF;
    const int r  = w - f * WPF;
    const int c  = r / SPC;           // chain id 0..22
    const int s  = r - c * SPC;       // segment 0..2
    const int col0 = c + CHPF * (SEG * s);   // first position col (<= 390)

    const float4* __restrict__ base = (const float4*)x;

    float4 tcur[9];     // rolling target row (36 regs)
    float  nt_cur;      // its reduced squared norm

    // Preload t_0 = row (f+1, col0+1)  (col0+1 <= 391, in range).
    {
        const float4* tp = base + (size_t)((f + 1) * TPF + col0 + 1) * ROWQ + lane;
        #pragma unroll
        for (int u = 0; u < 9; ++u) tcur[u] = tp[u * 32];
        float nt = 0.f;
        #pragma unroll
        for (int u = 0; u < 9; ++u) {
            nt = fmaf(tcur[u].x, tcur[u].x, nt); nt = fmaf(tcur[u].y, tcur[u].y, nt);
            nt = fmaf(tcur[u].z, tcur[u].z, nt); nt = fmaf(tcur[u].w, tcur[u].w, nt);
        }
        #pragma unroll
        for (int off = 16; off; off >>= 1) nt += __shfl_xor_sync(~0u, nt, off);
        nt_cur = nt;
    }

    #pragma unroll
    for (int m = 0; m < SEG; ++m) {
        const int colm = col0 + CHPF * m;
        const bool vr = (colm <= TPF - 2);          // right valid
        const bool vd = (colm <= TPF - WIDTH - 1);  // down valid
        const int coln = min(colm + WIDTH, TPF - 1); // clamped (masked if !vd)

        const float4* ap = base + (size_t)(f * TPF + colm) * ROWQ + lane;
        const float4* tp = base + (size_t)((f + 1) * TPF + coln) * ROWQ + lane;

        float dr = 0.f, dd = 0.f, na = 0.f, nt = 0.f;

        // 9 chunks in 3 bursts: 6 loads in flight per burst; t_cur chunk is
        // consumed (right dot) then overwritten by the t_next chunk.
        #pragma unroll
        for (int ch = 0; ch < 3; ++ch) {
            float4 av[3], tv[3];
            #pragma unroll
            for (int u = 0; u < 3; ++u) {
                const int k = ch * 3 + u;
                av[u] = ap[k * 32];
                tv[u] = tp[k * 32];
            }
            #pragma unroll
            for (int u = 0; u < 3; ++u) {
                const int k = ch * 3 + u;
                const float4 tc = tcur[k];
                dr = fmaf(av[u].x, tc.x, dr); dr = fmaf(av[u].y, tc.y, dr);
                dr = fmaf(av[u].z, tc.z, dr); dr = fmaf(av[u].w, tc.w, dr);
                dd = fmaf(av[u].x, tv[u].x, dd); dd = fmaf(av[u].y, tv[u].y, dd);
                dd = fmaf(av[u].z, tv[u].z, dd); dd = fmaf(av[u].w, tv[u].w, dd);
                na = fmaf(av[u].x, av[u].x, na); na = fmaf(av[u].y, av[u].y, na);
                na = fmaf(av[u].z, av[u].z, na); na = fmaf(av[u].w, av[u].w, na);
                nt = fmaf(tv[u].x, tv[u].x, nt); nt = fmaf(tv[u].y, tv[u].y, nt);
                nt = fmaf(tv[u].z, tv[u].z, nt); nt = fmaf(tv[u].w, tv[u].w, nt);
                tcur[k] = tv[u];
            }
        }

        #pragma unroll
        for (int off = 16; off; off >>= 1) {
            dr += __shfl_xor_sync(~0u, dr, off);
            dd += __shfl_xor_sync(~0u, dd, off);
            na += __shfl_xor_sync(~0u, na, off);
            nt += __shfl_xor_sync(~0u, nt, off);
        }

        if (lane == 0) {
            const float nA = fmaxf(sqrtf(na), EPS);
            float rr = -1.f, dn = -1.f;
            if (vr) rr = dr / (nA * fmaxf(sqrtf(nt_cur), EPS));
            if (vd) dn = dd / (nA * fmaxf(sqrtf(nt), EPS));
            out[f * TPF + colm]         = rr;
            out[TOTAL + f * TPF + colm] = dn;
        }
        nt_cur = nt;   // norm of the row now fully held in tcur
    }
}

// Frame 63 outputs are all -1 — chains only cover f <= 62.
__global__ void fill_last_frame(float* __restrict__ out) {
    const int idx = blockIdx.x * blockDim.x + threadIdx.x;
    if (idx < TPF) {
        out[(FRAMES - 1) * TPF + idx]         = -1.0f;
        out[TOTAL + (FRAMES - 1) * TPF + idx] = -1.0f;
    }
}

extern "C" void kernel_launch(void* const* d_in, const int* in_sizes, int n_in,
                              void* d_out, int out_size) {
    const float* x = (const float*)d_in[0];
    float* out = (float*)d_out;

    fill_last_frame<<<(TPF + 255) / 256, 256>>>(out);

    const int warps_per_block = 128 / 32;   // 4
    const int grid = (NWARPS + warps_per_block - 1) / warps_per_block; // 1087
    chain_kernel<<<grid, 128>>>(x, out);
}